// round 11
// baseline (speedup 1.0000x reference)
#include <cuda_runtime.h>
#include <math.h>
#include <stdint.h>

#define XF      1024
#define NB      2048
#define G       16
#define C4      (XF / 4)        // 256 float4 columns per row

// stats kernel geometry: 128 blocks x 512 threads.
#define GS      128
#define TS      512
#define RPT     (NB / (TS / 2)) // 8 rows per thread

__device__ float4 g_mean4 [C4];
__device__ float4 g_scale4[C4];
__device__ float4 g_shift4[C4];

// ──────────────────────────────────────────────────────────────────────────
// K1: column-strip stats (unchanged R9 winner). Block b owns float4-cols
// {2b, 2b+1} over the FULL batch; rows held in registers across both phases.
// ──────────────────────────────────────────────────────────────────────────
__global__ void __launch_bounds__(TS, 1) k_stats(const float* __restrict__ xf,
                                                 const float* __restrict__ wp) {
    const int t    = threadIdx.x;
    const int c    = t & 1;
    const int rg   = t >> 1;
    const int col4 = blockIdx.x * 2 + c;
    const float4* x4 = reinterpret_cast<const float4*>(xf);

    __shared__ float4 sA[TS];
    __shared__ float4 sB[TS];
    __shared__ float4 sMean[2];

    float4 xv[RPT];
    float4 a = make_float4(0.f, 0.f, 0.f, 0.f);
    #pragma unroll
    for (int i = 0; i < RPT; i++) {
        xv[i] = x4[(size_t)(rg * RPT + i) * C4 + col4];
        a.x += xv[i].x; a.y += xv[i].y; a.z += xv[i].z; a.w += xv[i].w;
    }
    sA[t] = a;
    __syncthreads();

    #pragma unroll
    for (int s = TS / 4; s > 0; s >>= 1) {
        if (rg < s) {
            float4 o = sA[(rg + s) * 2 + c];
            sA[t].x += o.x; sA[t].y += o.y; sA[t].z += o.z; sA[t].w += o.w;
        }
        __syncthreads();
    }
    if (rg == 0) {
        float4 m = sA[c];
        const float inv = 1.0f / NB;
        m.x *= inv; m.y *= inv; m.z *= inv; m.w *= inv;
        sMean[c] = m;
    }
    __syncthreads();
    const float4 m = sMean[c];

    float4 s  = make_float4(0.f, 0.f, 0.f, 0.f);
    float4 ss = make_float4(0.f, 0.f, 0.f, 0.f);
    #pragma unroll
    for (int i = 0; i < RPT; i++) {
        float4 v;
        v.x = fmaxf(xv[i].x - m.x, 0.f);
        v.y = fmaxf(xv[i].y - m.y, 0.f);
        v.z = fmaxf(xv[i].z - m.z, 0.f);
        v.w = fmaxf(xv[i].w - m.w, 0.f);
        s.x += v.x;       s.y += v.y;       s.z += v.z;       s.w += v.w;
        ss.x += v.x*v.x;  ss.y += v.y*v.y;  ss.z += v.z*v.z;  ss.w += v.w*v.w;
    }
    sA[t] = s;
    sB[t] = ss;
    __syncthreads();
    #pragma unroll
    for (int sN = TS / 4; sN > 0; sN >>= 1) {
        if (rg < sN) {
            float4 oa = sA[(rg + sN) * 2 + c];
            float4 ob = sB[(rg + sN) * 2 + c];
            sA[t].x += oa.x; sA[t].y += oa.y; sA[t].z += oa.z; sA[t].w += oa.w;
            sB[t].x += ob.x; sB[t].y += ob.y; sB[t].z += ob.z; sB[t].w += ob.w;
        }
        __syncthreads();
    }

    if (rg == 0) {
        const float w = wp[0];
        float4 S = sA[c], SS = sB[c];
        const float invN = 1.0f / NB, invN1 = 1.0f / (NB - 1);
        float4 sc, sh;
        {
            float mu = S.x * invN;
            float var = (SS.x - (float)NB * mu * mu) * invN1;
            sc.x = w / sqrtf(var); sh.x = -mu * sc.x;
        }
        {
            float mu = S.y * invN;
            float var = (SS.y - (float)NB * mu * mu) * invN1;
            sc.y = w / sqrtf(var); sh.y = -mu * sc.y;
        }
        {
            float mu = S.z * invN;
            float var = (SS.z - (float)NB * mu * mu) * invN1;
            sc.z = w / sqrtf(var); sh.z = -mu * sc.z;
        }
        {
            float mu = S.w * invN;
            float var = (SS.w - (float)NB * mu * mu) * invN1;
            sc.w = w / sqrtf(var); sh.w = -mu * sc.w;
        }
        g_mean4 [col4] = m;
        g_scale4[col4] = sc;
        g_shift4[col4] = sh;
    }
}

// ──────────────────────────────────────────────────────────────────────────
// K2: write pass via TMA bulk stores (bypasses the L1 store path, which ncu
// R9 showed as the binding pipe at 59.8%). One block per row: 256 threads
// compute the 1024-float normalized row once into SMEM, then one thread
// issues 16 async 4KB bulk copies (the G=16 tile = free replication from the
// same smem), commits, and waits only for smem-read completion.
// ──────────────────────────────────────────────────────────────────────────
__global__ void __launch_bounds__(256) k_write(const float* __restrict__ xf,
                                               float* __restrict__ out) {
    const int row = blockIdx.x;
    const int t   = threadIdx.x;

    __shared__ __align__(128) float srow[XF];

    float4 x  = reinterpret_cast<const float4*>(xf + (size_t)row * XF)[t];
    float4 m  = g_mean4 [t];
    float4 sc = g_scale4[t];
    float4 sh = g_shift4[t];

    float4 v;
    v.x = fmaxf(x.x - m.x, 0.f) * sc.x + sh.x;
    v.y = fmaxf(x.y - m.y, 0.f) * sc.y + sh.y;
    v.z = fmaxf(x.z - m.z, 0.f) * sc.z + sh.z;
    v.w = fmaxf(x.w - m.w, 0.f) * sc.w + sh.w;

    reinterpret_cast<float4*>(srow)[t] = v;
    __syncthreads();

    if (t == 0) {
        // order generic smem writes before async-proxy reads
        asm volatile("fence.proxy.async.shared::cta;" ::: "memory");

        uint32_t src;
        asm("{ .reg .u64 tmp; cvta.to.shared.u64 tmp, %1; cvt.u32.u64 %0, tmp; }"
            : "=r"(src) : "l"(srow));
        uint64_t dst = (uint64_t)(out + (size_t)row * XF * G);

        #pragma unroll
        for (int g = 0; g < G; g++) {
            asm volatile(
                "cp.async.bulk.global.shared::cta.bulk_group [%0], [%1], %2;"
                :: "l"(dst + (uint64_t)g * (XF * 4)), "r"(src), "n"(XF * 4)
                : "memory");
        }
        asm volatile("cp.async.bulk.commit_group;" ::: "memory");
        // wait only for SMEM reads to finish (writes drain independently);
        // block must not exit while TMA may still read its smem
        asm volatile("cp.async.bulk.wait_group.read 0;" ::: "memory");
    }
}

extern "C" void kernel_launch(void* const* d_in, const int* in_sizes, int n_in,
                              void* d_out, int out_size) {
    const float* xf = (const float*)d_in[0];   // [2048, 1024] f32
    const float* wp = (const float*)d_in[1];   // [1] f32
    float* out = (float*)d_out;                // [2048, 16384] f32

    k_stats<<<GS, TS>>>(xf, wp);
    k_write<<<NB, 256>>>(xf, out);
}

// round 12
// speedup vs baseline: 1.0620x; 1.0620x over previous
#include <cuda_runtime.h>
#include <math.h>
#include <stdint.h>

#define XF      1024
#define NB      2048
#define G       16
#define C4      (XF / 4)        // 256 float4 columns per row

// stats kernel geometry: 128 blocks x 512 threads.
#define GS      128
#define TS      512
#define RPT     (NB / (TS / 2)) // 8 rows per thread

__device__ float4 g_mean4 [C4];
__device__ float4 g_scale4[C4];
__device__ float4 g_shift4[C4];

// ──────────────────────────────────────────────────────────────────────────
// K1: column-strip stats (R9 winner) + early PDL trigger so K2 can launch
// and overlap its xf loads with this kernel's reduction work.
// ──────────────────────────────────────────────────────────────────────────
__global__ void __launch_bounds__(TS, 1) k_stats(const float* __restrict__ xf,
                                                 const float* __restrict__ wp) {
#if __CUDA_ARCH__ >= 900
    cudaTriggerProgrammaticLaunchCompletion();   // let k_write start loading xf now
#endif
    const int t    = threadIdx.x;
    const int c    = t & 1;
    const int rg   = t >> 1;
    const int col4 = blockIdx.x * 2 + c;
    const float4* x4 = reinterpret_cast<const float4*>(xf);

    __shared__ float4 sA[TS];
    __shared__ float4 sB[TS];
    __shared__ float4 sMean[2];

    float4 xv[RPT];
    float4 a = make_float4(0.f, 0.f, 0.f, 0.f);
    #pragma unroll
    for (int i = 0; i < RPT; i++) {
        xv[i] = x4[(size_t)(rg * RPT + i) * C4 + col4];
        a.x += xv[i].x; a.y += xv[i].y; a.z += xv[i].z; a.w += xv[i].w;
    }
    sA[t] = a;
    __syncthreads();

    #pragma unroll
    for (int s = TS / 4; s > 0; s >>= 1) {
        if (rg < s) {
            float4 o = sA[(rg + s) * 2 + c];
            sA[t].x += o.x; sA[t].y += o.y; sA[t].z += o.z; sA[t].w += o.w;
        }
        __syncthreads();
    }
    if (rg == 0) {
        float4 m = sA[c];
        const float inv = 1.0f / NB;
        m.x *= inv; m.y *= inv; m.z *= inv; m.w *= inv;
        sMean[c] = m;
    }
    __syncthreads();
    const float4 m = sMean[c];

    float4 s  = make_float4(0.f, 0.f, 0.f, 0.f);
    float4 ss = make_float4(0.f, 0.f, 0.f, 0.f);
    #pragma unroll
    for (int i = 0; i < RPT; i++) {
        float4 v;
        v.x = fmaxf(xv[i].x - m.x, 0.f);
        v.y = fmaxf(xv[i].y - m.y, 0.f);
        v.z = fmaxf(xv[i].z - m.z, 0.f);
        v.w = fmaxf(xv[i].w - m.w, 0.f);
        s.x += v.x;       s.y += v.y;       s.z += v.z;       s.w += v.w;
        ss.x += v.x*v.x;  ss.y += v.y*v.y;  ss.z += v.z*v.z;  ss.w += v.w*v.w;
    }
    sA[t] = s;
    sB[t] = ss;
    __syncthreads();
    #pragma unroll
    for (int sN = TS / 4; sN > 0; sN >>= 1) {
        if (rg < sN) {
            float4 oa = sA[(rg + sN) * 2 + c];
            float4 ob = sB[(rg + sN) * 2 + c];
            sA[t].x += oa.x; sA[t].y += oa.y; sA[t].z += oa.z; sA[t].w += oa.w;
            sB[t].x += ob.x; sB[t].y += ob.y; sB[t].z += ob.z; sB[t].w += ob.w;
        }
        __syncthreads();
    }

    if (rg == 0) {
        const float w = wp[0];
        float4 S = sA[c], SS = sB[c];
        const float invN = 1.0f / NB, invN1 = 1.0f / (NB - 1);
        float4 sc, sh;
        {
            float mu = S.x * invN;
            float var = (SS.x - (float)NB * mu * mu) * invN1;
            sc.x = w / sqrtf(var); sh.x = -mu * sc.x;
        }
        {
            float mu = S.y * invN;
            float var = (SS.y - (float)NB * mu * mu) * invN1;
            sc.y = w / sqrtf(var); sh.y = -mu * sc.y;
        }
        {
            float mu = S.z * invN;
            float var = (SS.z - (float)NB * mu * mu) * invN1;
            sc.z = w / sqrtf(var); sh.z = -mu * sc.z;
        }
        {
            float mu = S.w * invN;
            float var = (SS.w - (float)NB * mu * mu) * invN1;
            sc.w = w / sqrtf(var); sh.w = -mu * sc.w;
        }
        g_mean4 [col4] = m;
        g_scale4[col4] = sc;
        g_shift4[col4] = sh;
    }
}

// ──────────────────────────────────────────────────────────────────────────
// K2: write pass — R9 STG version (proven 22.1us, at LTS/store roofline),
// now with PDL: load xf (independent of k_stats) BEFORE the grid-dependency
// sync, then consume scale/shift after. Hides stats time + launch gap.
// ──────────────────────────────────────────────────────────────────────────
__global__ void __launch_bounds__(256) k_write(const float* __restrict__ xf,
                                               float* __restrict__ out) {
    const int row = blockIdx.x;
    const int t   = threadIdx.x;

    // independent work: pull this block's xf row while k_stats still runs
    float4 x = reinterpret_cast<const float4*>(xf + (size_t)row * XF)[t];

#if __CUDA_ARCH__ >= 900
    cudaGridDependencySynchronize();             // wait for k_stats completion
#endif

    float4 m  = g_mean4 [t];
    float4 sc = g_scale4[t];
    float4 sh = g_shift4[t];

    float4 v;
    v.x = fmaxf(x.x - m.x, 0.f) * sc.x + sh.x;
    v.y = fmaxf(x.y - m.y, 0.f) * sc.y + sh.y;
    v.z = fmaxf(x.z - m.z, 0.f) * sc.z + sh.z;
    v.w = fmaxf(x.w - m.w, 0.f) * sc.w + sh.w;

    float4* o = reinterpret_cast<float4*>(out + (size_t)row * XF * G) + t;
    #pragma unroll
    for (int g = 0; g < G; g++) {
        __stcs(o + g * C4, v);
    }
}

extern "C" void kernel_launch(void* const* d_in, const int* in_sizes, int n_in,
                              void* d_out, int out_size) {
    const float* xf = (const float*)d_in[0];   // [2048, 1024] f32
    const float* wp = (const float*)d_in[1];   // [1] f32
    float* out = (float*)d_out;                // [2048, 16384] f32

    k_stats<<<GS, TS>>>(xf, wp);

    cudaLaunchConfig_t cfg = {};
    cfg.gridDim  = dim3(NB, 1, 1);
    cfg.blockDim = dim3(256, 1, 1);
    cfg.dynamicSmemBytes = 0;
    cudaLaunchAttribute attr[1];
    attr[0].id = cudaLaunchAttributeProgrammaticStreamSerialization;
    attr[0].val.programmaticStreamSerializationAllowed = 1;
    cfg.attrs = attr;
    cfg.numAttrs = 1;
    cudaLaunchKernelEx(&cfg, k_write, xf, out);
}